// round 15
// baseline (speedup 1.0000x reference)
#include <cuda_runtime.h>
#include <cstddef>

// RecurrentLinearAttentionPPLM — NH=512; D=M=64; T=2048, T1=2049
// Inputs: query[NH,64], key[NH,64], value[NH,64], k_hist[NH,64,T], v_hist[NH,64,T]
// Output (flat concat): V[NH,64], K_cat[NH,64,T1], V_cat[NH,64,T1]
//
//   Qf = elu(q)+1, Kf = elu(k)+1
//   s[nh,j] = sum_d Qf[nh,d]*K_cat[nh,d,j] ;  Z = 1/(sum_j s + eps)
//   V[nh,m] = Z * sum_j s[nh,j]*V_cat[nh,m,j]
//
// Single fused launch; per-nh flag handshake (self-resetting).
// v-role register peak halved via two 4-quad batches split by column half
// (sa-batch then sb-batch) to enable 6 blocks/SM.

#define NH    512
#define TT    2048
#define T1    2049
#define T1P   2052
#define GRPW  8196            // words per 4-row output group
#define KBLK  (NH * 2)        // 1024 k-role blocks (1024-col chunks)
#define VBLK  (NH * 16)       // 8192 v-role blocks (4-row groups)
#define EPSF  1e-6f

__device__ float g_s [(size_t)NH * T1P];   // s row; tail (sT) at index TT
__device__ float g_zp[NH * 2];             // per-chunk partials of sum_j s
__device__ int   g_flag[NH];               // producer completion (0->2)
__device__ int   g_done[NH];               // consumer count (0->16 -> reset)

__global__ void __launch_bounds__(256, 6) k_fused(
    const float* __restrict__ q,  const float* __restrict__ k,
    const float* __restrict__ val,
    const float* __restrict__ kh, const float* __restrict__ vh,
    float* __restrict__ kcat, float* __restrict__ vcat,
    float* __restrict__ vout)
{
    __shared__ __align__(16) float smem[GRPW + 64];
    const int bid = blockIdx.x;
    const int t   = threadIdx.x;

    if (bid < KBLK) {
        // ------------- k-role: (nh, chunk c of 1024 cols) -------------
        const int nh = bid >> 1;
        const int c  = bid & 1;
        const int j0 = c << 10;

        float* qf_s  = smem;                    // 64
        float* kf_s  = smem + 64;               // 64
        float* stage = smem + 128;              // 2 x 2048 double buffer
        float* red   = smem + 128 + 4096;       // 8

        if (t < 64) {
            float qv = q[nh * 64 + t], kv = k[nh * 64 + t];
            qf_s[t] = qv > 0.f ? qv + 1.f : expf(qv);
            kf_s[t] = kv > 0.f ? kv + 1.f : expf(kv);
        }
        __syncthreads();

        const float* in      = kh   + (size_t)nh * 64 * TT + j0;
        float*       outbase = kcat + (size_t)nh * 64 * T1 + j0;

        float4 A0 = __ldcs((const float4*)(in) + t);
        float4 A1 = __ldcs((const float4*)(in + TT) + t);
        float s0 = 0.f, s1 = 0.f, s2 = 0.f, s3 = 0.f;

        for (int i = 0; i < 32; i++) {
            float4 B0, B1;
            if (i < 31) {
                B0 = __ldcs((const float4*)(in + (size_t)(2 * i + 2) * TT) + t);
                B1 = __ldcs((const float4*)(in + (size_t)(2 * i + 3) * TT) + t);
            }

            const float qd0 = qf_s[2 * i];
            const float qd1 = qf_s[2 * i + 1];
            s0 = fmaf(qd0, A0.x, s0); s1 = fmaf(qd0, A0.y, s1);
            s2 = fmaf(qd0, A0.z, s2); s3 = fmaf(qd0, A0.w, s3);
            s0 = fmaf(qd1, A1.x, s0); s1 = fmaf(qd1, A1.y, s1);
            s2 = fmaf(qd1, A1.z, s2); s3 = fmaf(qd1, A1.w, s3);

            float* st = stage + (i & 1) * 2048;
            ((float4*)st)[t]       = A0;
            ((float4*)st)[256 + t] = A1;
            __syncthreads();

            float* o0 = outbase + (size_t)(2 * i) * T1;
            float* o1 = o0 + T1;
            __stcs(o0 + t,       st[t]);
            __stcs(o0 + t + 256, st[t + 256]);
            __stcs(o0 + t + 512, st[t + 512]);
            __stcs(o0 + t + 768, st[t + 768]);
            __stcs(o1 + t,       st[1024 + t]);
            __stcs(o1 + t + 256, st[1024 + t + 256]);
            __stcs(o1 + t + 512, st[1024 + t + 512]);
            __stcs(o1 + t + 768, st[1024 + t + 768]);

            A0 = B0; A1 = B1;
        }

        ((float4*)(g_s + (size_t)nh * T1P + j0))[t] = make_float4(s0, s1, s2, s3);

        float v = s0 + s1 + s2 + s3;
        #pragma unroll
        for (int off = 16; off; off >>= 1) v += __shfl_down_sync(0xffffffffu, v, off);
        if ((t & 31) == 0) red[t >> 5] = v;
        __syncthreads();
        if (t == 0) {
            float tot = 0.f;
            #pragma unroll
            for (int w = 0; w < 8; w++) tot += red[w];
            g_zp[nh * 2 + c] = tot;
        }

        if (c == 1) {
            if (t < 64)
                kcat[(size_t)(nh * 64 + t) * T1 + TT] = kf_s[t];
            if (t == 0) {
                float sT = 0.f;
                #pragma unroll
                for (int d = 0; d < 64; d++) sT = fmaf(qf_s[d], kf_s[d], sT);
                g_s[(size_t)nh * T1P + TT] = sT;
            }
        }

        __threadfence();
        __syncthreads();
        if (t == 0) atomicAdd(&g_flag[nh], 1);

    } else {
        // ------------- v-role: (nh, 4-m-row group), two 4-quad batches -------------
        const int vb = bid - KBLK;
        const int nh = vb >> 4;
        const int m0 = (vb & 15) * 4;
        const int warp = t >> 5, lane = t & 31;

        float* stage = smem;                              // GRPW
        float (*red)[8] = (float (*)[8])(smem + GRPW);    // [4][8]

        const size_t rowbase = (size_t)nh * 64 + m0;
        const float4* in4 = (const float4*)(vh + rowbase * TT);

        // batch 1 (first halves of rows 0..3) issued before the spin
        float4 A0 = __ldcs(in4 + t);
        float4 A1 = __ldcs(in4 + t + 512);
        float4 A2 = __ldcs(in4 + t + 1024);
        float4 A3 = __ldcs(in4 + t + 1536);

        if (t == 0) {
            while (((volatile int*)g_flag)[nh] < 2) __nanosleep(64);
            __threadfence();
        }
        __syncthreads();   // acquire

        const float4* s4 = (const float4*)(g_s + (size_t)nh * T1P);
        float acc0, acc1, acc2, acc3;

        {   // consume batch 1 against sa
            const float4 sa = s4[t];
            acc0 = sa.x * A0.x + sa.y * A0.y + sa.z * A0.z + sa.w * A0.w;
            acc1 = sa.x * A1.x + sa.y * A1.y + sa.z * A1.z + sa.w * A1.w;
            acc2 = sa.x * A2.x + sa.y * A2.y + sa.z * A2.z + sa.w * A2.w;
            acc3 = sa.x * A3.x + sa.y * A3.y + sa.z * A3.z + sa.w * A3.w;
            int x = 4 * t;
            stage[x] = A0.x; stage[x + 1] = A0.y; stage[x + 2] = A0.z; stage[x + 3] = A0.w;
            x += T1;
            stage[x] = A1.x; stage[x + 1] = A1.y; stage[x + 2] = A1.z; stage[x + 3] = A1.w;
            x += T1;
            stage[x] = A2.x; stage[x + 1] = A2.y; stage[x + 2] = A2.z; stage[x + 3] = A2.w;
            x += T1;
            stage[x] = A3.x; stage[x + 1] = A3.y; stage[x + 2] = A3.z; stage[x + 3] = A3.w;
        }

        // batch 2 (second halves), registers reused
        A0 = __ldcs(in4 + t + 256);
        A1 = __ldcs(in4 + t + 768);
        A2 = __ldcs(in4 + t + 1280);
        A3 = __ldcs(in4 + t + 1792);

        {   // consume batch 2 against sb
            const float4 sb = s4[256 + t];
            acc0 += sb.x * A0.x + sb.y * A0.y + sb.z * A0.z + sb.w * A0.w;
            acc1 += sb.x * A1.x + sb.y * A1.y + sb.z * A1.z + sb.w * A1.w;
            acc2 += sb.x * A2.x + sb.y * A2.y + sb.z * A2.z + sb.w * A2.w;
            acc3 += sb.x * A3.x + sb.y * A3.y + sb.z * A3.z + sb.w * A3.w;
            int x = 1024 + 4 * t;
            stage[x] = A0.x; stage[x + 1] = A0.y; stage[x + 2] = A0.z; stage[x + 3] = A0.w;
            x += T1;
            stage[x] = A1.x; stage[x + 1] = A1.y; stage[x + 2] = A1.z; stage[x + 3] = A1.w;
            x += T1;
            stage[x] = A2.x; stage[x + 1] = A2.y; stage[x + 2] = A2.z; stage[x + 3] = A2.w;
            x += T1;
            stage[x] = A3.x; stage[x + 1] = A3.y; stage[x + 2] = A3.z; stage[x + 3] = A3.w;
        }

        if (t < 4) stage[t * T1 + TT] = val[rowbase + t];   // V_cat tail column

        {   // per-row warp reductions
            float vv;
            vv = acc0;
            #pragma unroll
            for (int off = 16; off; off >>= 1) vv += __shfl_down_sync(0xffffffffu, vv, off);
            if (lane == 0) red[0][warp] = vv;
            vv = acc1;
            #pragma unroll
            for (int off = 16; off; off >>= 1) vv += __shfl_down_sync(0xffffffffu, vv, off);
            if (lane == 0) red[1][warp] = vv;
            vv = acc2;
            #pragma unroll
            for (int off = 16; off; off >>= 1) vv += __shfl_down_sync(0xffffffffu, vv, off);
            if (lane == 0) red[2][warp] = vv;
            vv = acc3;
            #pragma unroll
            for (int off = 16; off; off >>= 1) vv += __shfl_down_sync(0xffffffffu, vv, off);
            if (lane == 0) red[3][warp] = vv;
        }
        __syncthreads();

        float4*       o4  = (float4*)(vcat + rowbase * T1);
        const float4* st4 = (const float4*)stage;
        #pragma unroll
        for (int u = 0; u < 8; u++) __stcs(o4 + t + 256 * u, st4[t + 256 * u]);
        if (t == 0) __stcs(o4 + 2048, st4[2048]);

        if (t < 4) {
            float tot = 0.f;
            #pragma unroll
            for (int w = 0; w < 8; w++) tot += red[t][w];
            const float sT    = g_s[(size_t)nh * T1P + TT];
            const float vlast = val[rowbase + t];
            const float zsum  = g_zp[nh * 2] + g_zp[nh * 2 + 1] + sT;
            vout[rowbase + t] = (tot + sT * vlast) / (zsum + EPSF);
        }

        // self-reset for graph replay: 16th consumer clears both counters
        if (t == 0) {
            int d = atomicAdd(&g_done[nh], 1);
            if (d == 15) { g_done[nh] = 0; g_flag[nh] = 0; }
        }
    }
}

// ---------------------------------------------------------------------------
extern "C" void kernel_launch(void* const* d_in, const int* in_sizes, int n_in,
                              void* d_out, int out_size)
{
    const float* q   = (const float*)d_in[0];
    const float* k   = (const float*)d_in[1];
    const float* val = (const float*)d_in[2];
    const float* kh  = (const float*)d_in[3];
    const float* vh  = (const float*)d_in[4];

    float* out  = (float*)d_out;
    float* vout = out;
    float* kcat = out + (size_t)NH * 64;
    float* vcat = kcat + (size_t)NH * 64 * T1;

    k_fused<<<KBLK + VBLK, 256>>>(q, k, val, kh, vh, kcat, vcat, vout);
}

// round 17
// speedup vs baseline: 1.2261x; 1.2261x over previous
#include <cuda_runtime.h>
#include <cstddef>

// RecurrentLinearAttentionPPLM — NH=512; D=M=64; T=2048, T1=2049
// Inputs: query[NH,64], key[NH,64], value[NH,64], k_hist[NH,64,T], v_hist[NH,64,T]
// Output (flat concat): V[NH,64], K_cat[NH,64,T1], V_cat[NH,64,T1]
//
//   Qf = elu(q)+1, Kf = elu(k)+1
//   s[nh,j] = sum_d Qf[nh,d]*K_cat[nh,d,j] ;  Z = 1/(sum_j s + eps)
//   V[nh,m] = Z * sum_j s[nh,j]*V_cat[nh,m,j]
//
// Single fused launch; per-nh flag handshake (self-resetting).
// R16 = proven R9 config (8-quad v-role MLP, 5 blocks/SM) + depth-2
// software pipeline in the k-role (6 quads in flight).

#define NH    512
#define TT    2048
#define T1    2049
#define T1P   2052
#define GRPW  8196            // words per 4-row output group
#define KBLK  (NH * 2)        // 1024 k-role blocks (1024-col chunks)
#define VBLK  (NH * 16)       // 8192 v-role blocks (4-row groups)
#define EPSF  1e-6f

__device__ float g_s [(size_t)NH * T1P];   // s row; tail (sT) at index TT
__device__ float g_zp[NH * 2];             // per-chunk partials of sum_j s
__device__ int   g_flag[NH];               // producer completion (0->2)
__device__ int   g_done[NH];               // consumer count (0->16 -> reset)

__global__ void __launch_bounds__(256, 5) k_fused(
    const float* __restrict__ q,  const float* __restrict__ k,
    const float* __restrict__ val,
    const float* __restrict__ kh, const float* __restrict__ vh,
    float* __restrict__ kcat, float* __restrict__ vcat,
    float* __restrict__ vout)
{
    __shared__ __align__(16) float smem[GRPW + 64];
    const int bid = blockIdx.x;
    const int t   = threadIdx.x;

    if (bid < KBLK) {
        // ------------- k-role: (nh, chunk c of 1024 cols) -------------
        const int nh = bid >> 1;
        const int c  = bid & 1;
        const int j0 = c << 10;

        float* qf_s  = smem;                    // 64
        float* kf_s  = smem + 64;               // 64
        float* stage = smem + 128;              // 2 x 2048 double buffer
        float* red   = smem + 128 + 4096;       // 8

        if (t < 64) {
            float qv = q[nh * 64 + t], kv = k[nh * 64 + t];
            qf_s[t] = qv > 0.f ? qv + 1.f : expf(qv);
            kf_s[t] = kv > 0.f ? kv + 1.f : expf(kv);
        }
        __syncthreads();

        const float* in      = kh   + (size_t)nh * 64 * TT + j0;
        float*       outbase = kcat + (size_t)nh * 64 * T1 + j0;

        // depth-2 pipeline: A = rows 2i, B = rows 2i+2, C = rows 2i+4
        float4 A0 = __ldcs((const float4*)(in) + t);
        float4 A1 = __ldcs((const float4*)(in + TT) + t);
        float4 B0 = __ldcs((const float4*)(in + 2 * TT) + t);
        float4 B1 = __ldcs((const float4*)(in + 3 * TT) + t);
        float s0 = 0.f, s1 = 0.f, s2 = 0.f, s3 = 0.f;

        for (int i = 0; i < 32; i++) {
            float4 C0, C1;
            if (i < 30) {
                C0 = __ldcs((const float4*)(in + (size_t)(2 * i + 4) * TT) + t);
                C1 = __ldcs((const float4*)(in + (size_t)(2 * i + 5) * TT) + t);
            }

            const float qd0 = qf_s[2 * i];
            const float qd1 = qf_s[2 * i + 1];
            s0 = fmaf(qd0, A0.x, s0); s1 = fmaf(qd0, A0.y, s1);
            s2 = fmaf(qd0, A0.z, s2); s3 = fmaf(qd0, A0.w, s3);
            s0 = fmaf(qd1, A1.x, s0); s1 = fmaf(qd1, A1.y, s1);
            s2 = fmaf(qd1, A1.z, s2); s3 = fmaf(qd1, A1.w, s3);

            float* st = stage + (i & 1) * 2048;
            ((float4*)st)[t]       = A0;
            ((float4*)st)[256 + t] = A1;
            __syncthreads();

            float* o0 = outbase + (size_t)(2 * i) * T1;
            float* o1 = o0 + T1;
            __stcs(o0 + t,       st[t]);
            __stcs(o0 + t + 256, st[t + 256]);
            __stcs(o0 + t + 512, st[t + 512]);
            __stcs(o0 + t + 768, st[t + 768]);
            __stcs(o1 + t,       st[1024 + t]);
            __stcs(o1 + t + 256, st[1024 + t + 256]);
            __stcs(o1 + t + 512, st[1024 + t + 512]);
            __stcs(o1 + t + 768, st[1024 + t + 768]);

            A0 = B0; A1 = B1;
            B0 = C0; B1 = C1;
        }

        ((float4*)(g_s + (size_t)nh * T1P + j0))[t] = make_float4(s0, s1, s2, s3);

        float v = s0 + s1 + s2 + s3;
        #pragma unroll
        for (int off = 16; off; off >>= 1) v += __shfl_down_sync(0xffffffffu, v, off);
        if ((t & 31) == 0) red[t >> 5] = v;
        __syncthreads();
        if (t == 0) {
            float tot = 0.f;
            #pragma unroll
            for (int w = 0; w < 8; w++) tot += red[w];
            g_zp[nh * 2 + c] = tot;
        }

        if (c == 1) {
            if (t < 64)
                kcat[(size_t)(nh * 64 + t) * T1 + TT] = kf_s[t];
            if (t == 0) {
                float sT = 0.f;
                #pragma unroll
                for (int d = 0; d < 64; d++) sT = fmaf(qf_s[d], kf_s[d], sT);
                g_s[(size_t)nh * T1P + TT] = sT;
            }
        }

        __threadfence();
        __syncthreads();
        if (t == 0) atomicAdd(&g_flag[nh], 1);

    } else {
        // ------------- v-role: (nh, 4-m-row group), 8 quads in flight -------------
        const int vb = bid - KBLK;
        const int nh = vb >> 4;
        const int m0 = (vb & 15) * 4;
        const int warp = t >> 5, lane = t & 31;

        float* stage = smem;                              // GRPW
        float (*red)[8] = (float (*)[8])(smem + GRPW);    // [4][8]

        const size_t rowbase = (size_t)nh * 64 + m0;
        const float4* in4  = (const float4*)(vh + rowbase * TT);
        float*        outp = vcat + rowbase * T1;

        // issue all DRAM loads BEFORE waiting — the spin hides behind them
        float4 A[8];
        #pragma unroll
        for (int u = 0; u < 8; u++) A[u] = __ldcs(in4 + t + 256 * u);

        if (t == 0) {
            while (((volatile int*)g_flag)[nh] < 2) __nanosleep(64);
            __threadfence();
        }
        __syncthreads();   // acquire for whole block

        const float4* s4 = (const float4*)(g_s + (size_t)nh * T1P);
        const float4 sa = s4[t];
        const float4 sb = s4[256 + t];

        float acc[4] = {0.f, 0.f, 0.f, 0.f};
        #pragma unroll
        for (int u = 0; u < 8; u++) {
            const int r = u >> 1;
            const float4 sv = (u & 1) ? sb : sa;
            float4 a = A[u];
            acc[r] = fmaf(sv.x, a.x, acc[r]);
            acc[r] = fmaf(sv.y, a.y, acc[r]);
            acc[r] = fmaf(sv.z, a.z, acc[r]);
            acc[r] = fmaf(sv.w, a.w, acc[r]);
            const int x = r * T1 + 4 * t + (u & 1) * 1024;
            stage[x] = a.x; stage[x + 1] = a.y; stage[x + 2] = a.z; stage[x + 3] = a.w;
        }
        if (t < 4) stage[t * T1 + TT] = val[rowbase + t];   // V_cat tail column

        #pragma unroll
        for (int r = 0; r < 4; r++) {
            float vv = acc[r];
            #pragma unroll
            for (int off = 16; off; off >>= 1) vv += __shfl_down_sync(0xffffffffu, vv, off);
            if (lane == 0) red[r][warp] = vv;
        }
        __syncthreads();

        float4*       o4  = (float4*)outp;
        const float4* st4 = (const float4*)stage;
        #pragma unroll
        for (int u = 0; u < 8; u++) __stcs(o4 + t + 256 * u, st4[t + 256 * u]);
        if (t == 0) __stcs(o4 + 2048, st4[2048]);

        if (t < 4) {
            float tot = 0.f;
            #pragma unroll
            for (int w = 0; w < 8; w++) tot += red[t][w];
            const float sT    = g_s[(size_t)nh * T1P + TT];
            const float vlast = val[rowbase + t];
            const float zsum  = g_zp[nh * 2] + g_zp[nh * 2 + 1] + sT;
            vout[rowbase + t] = (tot + sT * vlast) / (zsum + EPSF);
        }

        // self-reset for graph replay: 16th consumer clears both counters
        if (t == 0) {
            int d = atomicAdd(&g_done[nh], 1);
            if (d == 15) { g_done[nh] = 0; g_flag[nh] = 0; }
        }
    }
}

// ---------------------------------------------------------------------------
extern "C" void kernel_launch(void* const* d_in, const int* in_sizes, int n_in,
                              void* d_out, int out_size)
{
    const float* q   = (const float*)d_in[0];
    const float* k   = (const float*)d_in[1];
    const float* val = (const float*)d_in[2];
    const float* kh  = (const float*)d_in[3];
    const float* vh  = (const float*)d_in[4];

    float* out  = (float*)d_out;
    float* vout = out;
    float* kcat = out + (size_t)NH * 64;
    float* vcat = kcat + (size_t)NH * 64 * T1;

    k_fused<<<KBLK + VBLK, 256>>>(q, k, val, kh, vh, kcat, vcat, vout);
}